// round 6
// baseline (speedup 1.0000x reference)
#include <cuda_runtime.h>
#include <cuda_bf16.h>
#include <stdint.h>

// Shapes (fixed by the problem)
#define N_SEQ 256      // batch
#define NC    3        // coord channels
#define NT    256      // time
#define NV    25       // joints
#define NK    64       // structure elements
#define NROWS_SMEM 224 // key-matrix rows resident in K3 shared memory
#define INFK  0xFFFFFFFFu

// Scratch (device globals — no allocation allowed)
__device__ __align__(16) float    g_feat[N_SEQ * NV];
__device__ __align__(16) unsigned g_Dk[N_SEQ * N_SEQ];   // packed (dist24|idx8) keys

// ---------------------------------------------------------------------------
// K1: stage x[n] (76.8 KB) into smem with coalesced float4, then column sums.
// grid = 256 (one per n), block = 256, dyn smem = 76.8 KB (2 blocks/SM).
// ---------------------------------------------------------------------------
__global__ __launch_bounds__(256) void k_meanfeat(const float* __restrict__ x) {
    extern __shared__ __align__(16) float sx[];      // [768*25] staged rows
    __shared__ float s_part[8][NV];
    __shared__ float s_m[NV];

    const int n   = blockIdx.x;
    const int tid = threadIdx.x;
    const float4* xn4 = reinterpret_cast<const float4*>(x + (size_t)n * (NC * NT * NV));
    float4* sx4 = reinterpret_cast<float4*>(sx);

    // coalesced stage: 4800 float4 / 256 threads (MLP ~19 per thread)
    #pragma unroll 4
    for (int idx = tid; idx < (NC * NT * NV) / 4; idx += 256)
        sx4[idx] = xn4[idx];
    __syncthreads();

    // column sums: 8 groups x 25 threads, each group sums a 96-row chunk
    if (tid < 200) {
        const int g = tid / 25, v = tid - g * 25;
        const int r0 = g * 96;
        float a0 = 0.f, a1 = 0.f, a2 = 0.f, a3 = 0.f;
        #pragma unroll
        for (int i = 0; i < 24; i++) {
            a0 += sx[(r0      + i) * NV + v];
            a1 += sx[(r0 + 24 + i) * NV + v];
            a2 += sx[(r0 + 48 + i) * NV + v];
            a3 += sx[(r0 + 72 + i) * NV + v];
        }
        s_part[g][v] = (a0 + a1) + (a2 + a3);
    }
    __syncthreads();

    if (tid < NV) {
        float s = 0.f;
        #pragma unroll
        for (int g = 0; g < 8; g++) s += s_part[g][tid];
        s_m[tid] = s * (1.0f / (NC * NT));
    }
    __syncthreads();

    if (tid < NV) {
        const float mj = s_m[tid];
        float ss = 0.f;
        #pragma unroll
        for (int i = 0; i < NV; i++) {
            float d = s_m[i] - mj;
            ss += d * d;
        }
        g_feat[n * NV + tid] = sqrtf(ss);
    }
}

// ---------------------------------------------------------------------------
// K2: global min/max normalization + PACKED distance-key matrix row i
// key[i][j] = (float_bits(D[i][j]) & 0xFFFFFF00) | j
// grid = 256 (row i), block = 256 (col j)
// ---------------------------------------------------------------------------
__global__ __launch_bounds__(256) void k_dist() {
    const int i   = blockIdx.x;
    const int tid = threadIdx.x;

    __shared__ float sf[N_SEQ * NV];          // 25.6 KB, all features
    __shared__ unsigned smin[8], smax[8];

    for (int idx = tid; idx < N_SEQ * NV; idx += 256)
        sf[idx] = g_feat[idx];
    __syncthreads();

    // global min/max (feat >= 0, so uint order == float order)
    unsigned lmin = INFK, lmax = 0u;
    for (int idx = tid; idx < N_SEQ * NV; idx += 256) {
        unsigned b = __float_as_uint(sf[idx]);
        lmin = min(lmin, b);
        lmax = max(lmax, b);
    }
    lmin = __reduce_min_sync(0xFFFFFFFFu, lmin);
    lmax = __reduce_max_sync(0xFFFFFFFFu, lmax);
    if ((tid & 31) == 0) { smin[tid >> 5] = lmin; smax[tid >> 5] = lmax; }
    __syncthreads();
    unsigned gmn = smin[0], gmx = smax[0];
    #pragma unroll
    for (int w = 1; w < 8; w++) { gmn = min(gmn, smin[w]); gmx = max(gmx, smax[w]); }
    const float inv = 1.0f / (__uint_as_float(gmx) - __uint_as_float(gmn));

    // row i (broadcast from smem) vs col j = tid
    float fi[NV];
    #pragma unroll
    for (int d = 0; d < NV; d++) fi[d] = sf[i * NV + d];

    float ss = 0.f;
    #pragma unroll
    for (int d = 0; d < NV; d++) {
        float df = (fi[d] - sf[tid * NV + d]) * inv;
        ss += df * df;
    }
    g_Dk[i * N_SEQ + tid] = (__float_as_uint(sqrtf(ss)) & 0xFFFFFF00u) | (unsigned)tid;
}

// ---------------------------------------------------------------------------
// K3: single-warp Prim MST, branch-free row fetch (predicated pointer select +
//     generic LD), pre-packed keys, bare redux. + structure element epilogue.
// grid = 1, block = 512, dyn smem = 224 KB
// ---------------------------------------------------------------------------
__global__ __launch_bounds__(512) void k_mst(const float* __restrict__ centres,
                                             const float* __restrict__ sharp,
                                             float* __restrict__ out) {
    extern __shared__ __align__(16) unsigned sKey[];   // NROWS_SMEM rows of keys
    __shared__ float deaths[N_SEQ - 1];
    __shared__ float s_part2[8][NK];

    const int tid = threadIdx.x;

    // Fill smem rows 0..NROWS_SMEM-1 (vectorized uint4, 512 threads).
    {
        uint4*       s4 = reinterpret_cast<uint4*>(sKey);
        const uint4* g4 = reinterpret_cast<const uint4*>(g_Dk);
        const int nfill = NROWS_SMEM * (N_SEQ / 4);
        #pragma unroll 4
        for (int idx = tid; idx < nfill; idx += 512) s4[idx] = g4[idx];
    }
    __syncthreads();

    // ---- Prim's MST on warp 0: 8 nodes per lane, keys in named registers ----
    if (tid < 32) {
        const int lane = tid;
        const int base = lane * 8;

        unsigned k0 = sKey[base + 0], k1 = sKey[base + 1];
        unsigned k2 = sKey[base + 2], k3 = sKey[base + 3];
        unsigned k4 = sKey[base + 4], k5 = sKey[base + 5];
        unsigned k6 = sKey[base + 6], k7 = sKey[base + 7];
        if (lane == 0) k0 = INFK;   // node 0 starts in the tree

        for (int it = 0; it < N_SEQ - 1; ++it) {
            // lane-local min8 (depth-3 tree), then bare warp redux
            unsigned m = min(min(min(k0, k1), min(k2, k3)),
                             min(min(k4, k5), min(k6, k7)));
            unsigned g;
            asm volatile("redux.sync.min.u32 %0, %1, 0xffffffff;"
                         : "=r"(g) : "r"(m));
            const int j = (int)(g & 0xFFu);
            if (lane == 0) deaths[it] = __uint_as_float(g & 0xFFFFFF00u);

            // branch-free row fetch: predicated pointer select + generic LD.128
            const uint4* rp = (j < NROWS_SMEM)
                ? reinterpret_cast<const uint4*>(sKey + j * N_SEQ + base)
                : reinterpret_cast<const uint4*>(g_Dk + j * N_SEQ + base);
            uint4 ra = rp[0];
            uint4 rb = rp[1];

            // update: min with pre-packed candidate; in-tree stays INF;
            // extracted node j -> INF. All register indices static.
            #define UPD(K, PK) { \
                unsigned nk = min(k##K, (PK)); \
                nk = (k##K == INFK) ? INFK : nk; \
                k##K = ((base + K) == j) ? INFK : nk; }
            UPD(0, ra.x) UPD(1, ra.y) UPD(2, ra.z) UPD(3, ra.w)
            UPD(4, rb.x) UPD(5, rb.y) UPD(6, rb.z) UPD(7, rb.w)
            #undef UPD
        }
    }
    __syncthreads();

    // ---- Structure element layer: out[k] = sum_e exp(-(c0^2 s0^2 + (w_e-c1)^2 s1^2))
    {
        const int k    = tid & (NK - 1);
        const int part = tid >> 6;            // 0..7
        const float c0 = centres[2 * k];
        const float c1 = centres[2 * k + 1];
        const float s0 = sharp[2 * k];
        const float s1 = sharp[2 * k + 1];
        const float a  = c0 * c0 * s0 * s0;
        const float b  = s1 * s1;

        float acc = 0.f;
        const int e0 = part * 32;
        const int e1 = min(N_SEQ - 1, e0 + 32);
        for (int e = e0; e < e1; e++) {
            float d = deaths[e] - c1;
            acc += __expf(-(a + d * d * b));
        }
        s_part2[part][k] = acc;
    }
    __syncthreads();
    if (tid < NK) {
        float s = 0.f;
        #pragma unroll
        for (int p = 0; p < 8; p++) s += s_part2[p][tid];
        out[tid] = s;
    }
}

// ---------------------------------------------------------------------------
extern "C" void kernel_launch(void* const* d_in, const int* in_sizes, int n_in,
                              void* d_out, int out_size) {
    const float* x       = (const float*)d_in[0];
    const float* centres = (const float*)d_in[1];
    const float* sharp   = (const float*)d_in[2];
    float*       out     = (float*)d_out;

    const size_t k1_smem  = (size_t)NC * NT * NV * sizeof(float);          // 76.8 KB
    const size_t mst_smem = (size_t)NROWS_SMEM * N_SEQ * sizeof(unsigned); // 224 KB
    cudaFuncSetAttribute(k_meanfeat, cudaFuncAttributeMaxDynamicSharedMemorySize, (int)k1_smem);
    cudaFuncSetAttribute(k_mst,      cudaFuncAttributeMaxDynamicSharedMemorySize, (int)mst_smem);

    k_meanfeat<<<N_SEQ, 256, k1_smem>>>(x);
    k_dist<<<N_SEQ, 256>>>();
    k_mst<<<1, 512, mst_smem>>>(centres, sharp, out);
}

// round 7
// speedup vs baseline: 1.0870x; 1.0870x over previous
#include <cuda_runtime.h>
#include <cuda_bf16.h>
#include <stdint.h>

// Shapes (fixed by the problem)
#define N_SEQ 256      // batch
#define NC    3        // coord channels
#define NT    256      // time
#define NV    25       // joints
#define NK    64       // structure elements
#define NROWS_SMEM 224 // key-matrix rows resident in K3 shared memory
#define INFK  0xFFFFFFFFu

// Scratch (device globals — no allocation allowed)
__device__ __align__(16) float    g_feat[N_SEQ * NV];
__device__ __align__(16) unsigned g_Dk[N_SEQ * N_SEQ];   // packed (dist24|idx8) keys

// ---------------------------------------------------------------------------
// K1: stage x[n] (76.8 KB) into smem with coalesced float4, then column sums.
// grid = 256 (one per n), block = 256, dyn smem = 76.8 KB (2 blocks/SM).
// ---------------------------------------------------------------------------
__global__ __launch_bounds__(256) void k_meanfeat(const float* __restrict__ x) {
    extern __shared__ __align__(16) float sx[];      // [768*25] staged rows
    __shared__ float s_part[8][NV];
    __shared__ float s_m[NV];

    const int n   = blockIdx.x;
    const int tid = threadIdx.x;
    const float4* xn4 = reinterpret_cast<const float4*>(x + (size_t)n * (NC * NT * NV));
    float4* sx4 = reinterpret_cast<float4*>(sx);

    // coalesced stage: 4800 float4 / 256 threads (MLP ~19 per thread)
    #pragma unroll 4
    for (int idx = tid; idx < (NC * NT * NV) / 4; idx += 256)
        sx4[idx] = xn4[idx];
    __syncthreads();

    // column sums: 8 groups x 25 threads, each group sums a 96-row chunk
    if (tid < 200) {
        const int g = tid / 25, v = tid - g * 25;
        const int r0 = g * 96;
        float a0 = 0.f, a1 = 0.f, a2 = 0.f, a3 = 0.f;
        #pragma unroll
        for (int i = 0; i < 24; i++) {
            a0 += sx[(r0      + i) * NV + v];
            a1 += sx[(r0 + 24 + i) * NV + v];
            a2 += sx[(r0 + 48 + i) * NV + v];
            a3 += sx[(r0 + 72 + i) * NV + v];
        }
        s_part[g][v] = (a0 + a1) + (a2 + a3);
    }
    __syncthreads();

    if (tid < NV) {
        float s = 0.f;
        #pragma unroll
        for (int g = 0; g < 8; g++) s += s_part[g][tid];
        s_m[tid] = s * (1.0f / (NC * NT));
    }
    __syncthreads();

    if (tid < NV) {
        const float mj = s_m[tid];
        float ss = 0.f;
        #pragma unroll
        for (int i = 0; i < NV; i++) {
            float d = s_m[i] - mj;
            ss += d * d;
        }
        g_feat[n * NV + tid] = sqrtf(ss);
    }
}

// ---------------------------------------------------------------------------
// K2: global min/max normalization + PACKED distance-key matrix row i
// key[i][j] = (float_bits(D[i][j]) & 0xFFFFFF00) | j
// grid = 256 (row i), block = 256 (col j)
// ---------------------------------------------------------------------------
__global__ __launch_bounds__(256) void k_dist() {
    const int i   = blockIdx.x;
    const int tid = threadIdx.x;

    __shared__ float sf[N_SEQ * NV];          // 25.6 KB, all features
    __shared__ unsigned smin[8], smax[8];

    for (int idx = tid; idx < N_SEQ * NV; idx += 256)
        sf[idx] = g_feat[idx];
    __syncthreads();

    // global min/max (feat >= 0, so uint order == float order)
    unsigned lmin = INFK, lmax = 0u;
    for (int idx = tid; idx < N_SEQ * NV; idx += 256) {
        unsigned b = __float_as_uint(sf[idx]);
        lmin = min(lmin, b);
        lmax = max(lmax, b);
    }
    lmin = __reduce_min_sync(0xFFFFFFFFu, lmin);
    lmax = __reduce_max_sync(0xFFFFFFFFu, lmax);
    if ((tid & 31) == 0) { smin[tid >> 5] = lmin; smax[tid >> 5] = lmax; }
    __syncthreads();
    unsigned gmn = smin[0], gmx = smax[0];
    #pragma unroll
    for (int w = 1; w < 8; w++) { gmn = min(gmn, smin[w]); gmx = max(gmx, smax[w]); }
    const float inv = 1.0f / (__uint_as_float(gmx) - __uint_as_float(gmn));

    // row i (broadcast from smem) vs col j = tid
    float fi[NV];
    #pragma unroll
    for (int d = 0; d < NV; d++) fi[d] = sf[i * NV + d];

    float ss = 0.f;
    #pragma unroll
    for (int d = 0; d < NV; d++) {
        float df = (fi[d] - sf[tid * NV + d]) * inv;
        ss += df * df;
    }
    g_Dk[i * N_SEQ + tid] = (__float_as_uint(sqrtf(ss)) & 0xFFFFFF00u) | (unsigned)tid;
}

// ---------------------------------------------------------------------------
// K3: single-warp Prim MST, branch-free row fetch (predicated pointer select +
//     generic LD), pre-packed keys, bare redux. + structure element epilogue.
// grid = 1, block = 512, dyn smem = 224 KB
// ---------------------------------------------------------------------------
__global__ __launch_bounds__(512) void k_mst(const float* __restrict__ centres,
                                             const float* __restrict__ sharp,
                                             float* __restrict__ out) {
    extern __shared__ __align__(16) unsigned sKey[];   // NROWS_SMEM rows of keys
    __shared__ float deaths[N_SEQ - 1];
    __shared__ float s_part2[8][NK];

    const int tid = threadIdx.x;

    // Fill smem rows 0..NROWS_SMEM-1 (vectorized uint4, 512 threads).
    {
        uint4*       s4 = reinterpret_cast<uint4*>(sKey);
        const uint4* g4 = reinterpret_cast<const uint4*>(g_Dk);
        const int nfill = NROWS_SMEM * (N_SEQ / 4);
        #pragma unroll 4
        for (int idx = tid; idx < nfill; idx += 512) s4[idx] = g4[idx];
    }
    __syncthreads();

    // ---- Prim's MST on warp 0: 8 nodes per lane, keys in named registers ----
    if (tid < 32) {
        const int lane = tid;
        const int base = lane * 8;

        unsigned k0 = sKey[base + 0], k1 = sKey[base + 1];
        unsigned k2 = sKey[base + 2], k3 = sKey[base + 3];
        unsigned k4 = sKey[base + 4], k5 = sKey[base + 5];
        unsigned k6 = sKey[base + 6], k7 = sKey[base + 7];
        if (lane == 0) k0 = INFK;   // node 0 starts in the tree

        for (int it = 0; it < N_SEQ - 1; ++it) {
            // lane-local min8 (depth-3 tree), then bare warp redux
            unsigned m = min(min(min(k0, k1), min(k2, k3)),
                             min(min(k4, k5), min(k6, k7)));
            unsigned g;
            asm volatile("redux.sync.min.u32 %0, %1, 0xffffffff;"
                         : "=r"(g) : "r"(m));
            const int j = (int)(g & 0xFFu);
            if (lane == 0) deaths[it] = __uint_as_float(g & 0xFFFFFF00u);

            // branch-free row fetch: predicated pointer select + generic LD.128
            const uint4* rp = (j < NROWS_SMEM)
                ? reinterpret_cast<const uint4*>(sKey + j * N_SEQ + base)
                : reinterpret_cast<const uint4*>(g_Dk + j * N_SEQ + base);
            uint4 ra = rp[0];
            uint4 rb = rp[1];

            // update: min with pre-packed candidate; in-tree stays INF;
            // extracted node j -> INF. All register indices static.
            #define UPD(K, PK) { \
                unsigned nk = min(k##K, (PK)); \
                nk = (k##K == INFK) ? INFK : nk; \
                k##K = ((base + K) == j) ? INFK : nk; }
            UPD(0, ra.x) UPD(1, ra.y) UPD(2, ra.z) UPD(3, ra.w)
            UPD(4, rb.x) UPD(5, rb.y) UPD(6, rb.z) UPD(7, rb.w)
            #undef UPD
        }
    }
    __syncthreads();

    // ---- Structure element layer: out[k] = sum_e exp(-(c0^2 s0^2 + (w_e-c1)^2 s1^2))
    {
        const int k    = tid & (NK - 1);
        const int part = tid >> 6;            // 0..7
        const float c0 = centres[2 * k];
        const float c1 = centres[2 * k + 1];
        const float s0 = sharp[2 * k];
        const float s1 = sharp[2 * k + 1];
        const float a  = c0 * c0 * s0 * s0;
        const float b  = s1 * s1;

        float acc = 0.f;
        const int e0 = part * 32;
        const int e1 = min(N_SEQ - 1, e0 + 32);
        for (int e = e0; e < e1; e++) {
            float d = deaths[e] - c1;
            acc += __expf(-(a + d * d * b));
        }
        s_part2[part][k] = acc;
    }
    __syncthreads();
    if (tid < NK) {
        float s = 0.f;
        #pragma unroll
        for (int p = 0; p < 8; p++) s += s_part2[p][tid];
        out[tid] = s;
    }
}

// ---------------------------------------------------------------------------
extern "C" void kernel_launch(void* const* d_in, const int* in_sizes, int n_in,
                              void* d_out, int out_size) {
    const float* x       = (const float*)d_in[0];
    const float* centres = (const float*)d_in[1];
    const float* sharp   = (const float*)d_in[2];
    float*       out     = (float*)d_out;

    const size_t k1_smem  = (size_t)NC * NT * NV * sizeof(float);          // 76.8 KB
    const size_t mst_smem = (size_t)NROWS_SMEM * N_SEQ * sizeof(unsigned); // 224 KB
    cudaFuncSetAttribute(k_meanfeat, cudaFuncAttributeMaxDynamicSharedMemorySize, (int)k1_smem);
    cudaFuncSetAttribute(k_mst,      cudaFuncAttributeMaxDynamicSharedMemorySize, (int)mst_smem);

    k_meanfeat<<<N_SEQ, 256, k1_smem>>>(x);
    k_dist<<<N_SEQ, 256>>>();
    k_mst<<<1, 512, mst_smem>>>(centres, sharp, out);
}

// round 8
// speedup vs baseline: 1.1453x; 1.0536x over previous
#include <cuda_runtime.h>
#include <cuda_bf16.h>
#include <stdint.h>

// Shapes (fixed by the problem)
#define N_SEQ 256      // batch
#define NC    3        // coord channels
#define NT    256      // time
#define NV    25       // joints
#define NK    64       // structure elements
#define NROWS_SMEM 224 // key-matrix rows resident in K3 shared memory
#define INFK  0xFFFFFFFFu

// Scratch (device globals — no allocation allowed)
__device__ __align__(16) float    g_feat[N_SEQ * NV];
__device__ __align__(16) unsigned g_Dk[N_SEQ * N_SEQ];   // packed (dist24|idx8) keys

// ---------------------------------------------------------------------------
// K1: per-sequence mean over (c,t), then feat[n,j] = || m[n,:] - m[n,j] ||
// grid = 256 (one per n), block = 512 (16 warps). Each warp sums 48 rows with
// 8 accumulators, FULLY unrolled -> front-batched LDGs, high MLP.
// ---------------------------------------------------------------------------
__global__ __launch_bounds__(512) void k_meanfeat(const float* __restrict__ x) {
    __shared__ float s_part[16][NV];
    __shared__ float s_m[NV];

    const int n    = blockIdx.x;
    const int tid  = threadIdx.x;
    const int w    = tid >> 5;
    const int lane = tid & 31;

    if (lane < NV) {
        const float* p = x + (size_t)n * (NC * NT * NV) + w * 48 * NV + lane;
        float a0 = 0.f, a1 = 0.f, a2 = 0.f, a3 = 0.f;
        float a4 = 0.f, a5 = 0.f, a6 = 0.f, a7 = 0.f;
        #pragma unroll
        for (int i = 0; i < 6; i++) {
            const float* q = p + i * 8 * NV;
            a0 += q[0 * NV]; a1 += q[1 * NV]; a2 += q[2 * NV]; a3 += q[3 * NV];
            a4 += q[4 * NV]; a5 += q[5 * NV]; a6 += q[6 * NV]; a7 += q[7 * NV];
        }
        s_part[w][lane] = ((a0 + a1) + (a2 + a3)) + ((a4 + a5) + (a6 + a7));
    }
    __syncthreads();

    if (tid < NV) {
        float s = 0.f;
        #pragma unroll
        for (int ww = 0; ww < 16; ww++) s += s_part[ww][tid];
        s_m[tid] = s * (1.0f / (NC * NT));
    }
    __syncthreads();

    if (tid < NV) {
        const float mj = s_m[tid];
        float ss = 0.f;
        #pragma unroll
        for (int i = 0; i < NV; i++) {
            float d = s_m[i] - mj;
            ss += d * d;
        }
        g_feat[n * NV + tid] = sqrtf(ss);
    }
}

// ---------------------------------------------------------------------------
// K2: global min/max normalization + PACKED distance-key matrix row i
// key[i][j] = (float_bits(D[i][j]) & 0xFFFFFF00) | j
// grid = 256 (row i), block = 256 (col j)
// ---------------------------------------------------------------------------
__global__ __launch_bounds__(256) void k_dist() {
    const int i   = blockIdx.x;
    const int tid = threadIdx.x;

    __shared__ float sf[N_SEQ * NV];          // 25.6 KB, all features
    __shared__ unsigned smin[8], smax[8];

    for (int idx = tid; idx < N_SEQ * NV; idx += 256)
        sf[idx] = g_feat[idx];
    __syncthreads();

    // global min/max (feat >= 0, so uint order == float order)
    unsigned lmin = INFK, lmax = 0u;
    for (int idx = tid; idx < N_SEQ * NV; idx += 256) {
        unsigned b = __float_as_uint(sf[idx]);
        lmin = min(lmin, b);
        lmax = max(lmax, b);
    }
    lmin = __reduce_min_sync(0xFFFFFFFFu, lmin);
    lmax = __reduce_max_sync(0xFFFFFFFFu, lmax);
    if ((tid & 31) == 0) { smin[tid >> 5] = lmin; smax[tid >> 5] = lmax; }
    __syncthreads();
    unsigned gmn = smin[0], gmx = smax[0];
    #pragma unroll
    for (int w = 1; w < 8; w++) { gmn = min(gmn, smin[w]); gmx = max(gmx, smax[w]); }
    const float inv = 1.0f / (__uint_as_float(gmx) - __uint_as_float(gmn));

    // row i (broadcast from smem) vs col j = tid
    float fi[NV];
    #pragma unroll
    for (int d = 0; d < NV; d++) fi[d] = sf[i * NV + d];

    float ss = 0.f;
    #pragma unroll
    for (int d = 0; d < NV; d++) {
        float df = (fi[d] - sf[tid * NV + d]) * inv;
        ss += df * df;
    }
    g_Dk[i * N_SEQ + tid] = (__float_as_uint(sqrtf(ss)) & 0xFFFFFF00u) | (unsigned)tid;
}

// ---------------------------------------------------------------------------
// K3: single-warp Prim MST with SHORTENED critical chain:
//   min8(min(k,cand)) == min( min8(keys after j-removal), min8(cand) )
// so the key-removal + m_fix recompute runs OFF-chain under the row load,
// and post-load work is just SEL + min8 tree + 1 min.
// grid = 1, block = 512, dyn smem = 224 KB
// ---------------------------------------------------------------------------
__global__ __launch_bounds__(512) void k_mst(const float* __restrict__ centres,
                                             const float* __restrict__ sharp,
                                             float* __restrict__ out) {
    extern __shared__ __align__(16) unsigned sKey[];   // NROWS_SMEM rows of keys
    __shared__ float deaths[N_SEQ - 1];
    __shared__ float s_part2[8][NK];

    const int tid = threadIdx.x;

    // Fill smem rows 0..NROWS_SMEM-1 (vectorized uint4, 512 threads).
    {
        uint4*       s4 = reinterpret_cast<uint4*>(sKey);
        const uint4* g4 = reinterpret_cast<const uint4*>(g_Dk);
        const int nfill = NROWS_SMEM * (N_SEQ / 4);
        #pragma unroll 4
        for (int idx = tid; idx < nfill; idx += 512) s4[idx] = g4[idx];
    }
    __syncthreads();

    // ---- Prim's MST on warp 0: 8 nodes per lane, keys in named registers ----
    if (tid < 32) {
        const int lane = tid;
        const int base = lane * 8;

        // per-lane byte base pointers (lane offset folded in)
        const char* sB = reinterpret_cast<const char*>(sKey) + base * 4;
        const char* gB = reinterpret_cast<const char*>(g_Dk) + base * 4;

        unsigned k0 = sKey[base + 0], k1 = sKey[base + 1];
        unsigned k2 = sKey[base + 2], k3 = sKey[base + 3];
        unsigned k4 = sKey[base + 4], k5 = sKey[base + 5];
        unsigned k6 = sKey[base + 6], k7 = sKey[base + 7];
        if (lane == 0) k0 = INFK;   // node 0 starts in the tree

        unsigned m = min(min(min(k0, k1), min(k2, k3)),
                         min(min(k4, k5), min(k6, k7)));

        for (int it = 0; it < N_SEQ - 1; ++it) {
            unsigned g;
            asm volatile("redux.sync.min.u32 %0, %1, 0xffffffff;"
                         : "=r"(g) : "r"(m));
            const int j = (int)(g & 0xFFu);
            if (lane == 0) deaths[it] = __uint_as_float(g & 0xFFFFFF00u);

            // branch-free row fetch (chain): pointer data-select + generic LD.128
            const char*  bp = (j < NROWS_SMEM) ? sB : gB;
            const uint4* rp = reinterpret_cast<const uint4*>(bp + ((unsigned)j << 10));
            const uint4  ra = rp[0];
            const uint4  rb = rp[1];

            // OFF-chain (under the load): remove node j from this lane's keys,
            // recompute m_fix = min8(keys).
            const bool own = ((j >> 3) == lane);
            const int  jk  = j & 7;
            #define RM(K) k##K = (own && (jk == K)) ? INFK : k##K;
            RM(0) RM(1) RM(2) RM(3) RM(4) RM(5) RM(6) RM(7)
            #undef RM
            const unsigned mfix = min(min(min(k0, k1), min(k2, k3)),
                                      min(min(k4, k5), min(k6, k7)));

            // ON-chain: mask row candidates (in-tree -> INF), merge.
            #define CM(K, RV) \
                const unsigned c##K = (k##K == INFK) ? INFK : (RV); \
                k##K = min(k##K, c##K);
            CM(0, ra.x) CM(1, ra.y) CM(2, ra.z) CM(3, ra.w)
            CM(4, rb.x) CM(5, rb.y) CM(6, rb.z) CM(7, rb.w)
            #undef CM
            const unsigned mc = min(min(min(c0, c1), min(c2, c3)),
                                    min(min(c4, c5), min(c6, c7)));
            m = min(mfix, mc);
        }
    }
    __syncthreads();

    // ---- Structure element layer: out[k] = sum_e exp(-(c0^2 s0^2 + (w_e-c1)^2 s1^2))
    {
        const int k    = tid & (NK - 1);
        const int part = tid >> 6;            // 0..7
        const float c0 = centres[2 * k];
        const float c1 = centres[2 * k + 1];
        const float s0 = sharp[2 * k];
        const float s1 = sharp[2 * k + 1];
        const float a  = c0 * c0 * s0 * s0;
        const float b  = s1 * s1;

        float acc = 0.f;
        const int e0 = part * 32;
        const int e1 = min(N_SEQ - 1, e0 + 32);
        for (int e = e0; e < e1; e++) {
            float d = deaths[e] - c1;
            acc += __expf(-(a + d * d * b));
        }
        s_part2[part][k] = acc;
    }
    __syncthreads();
    if (tid < NK) {
        float s = 0.f;
        #pragma unroll
        for (int p = 0; p < 8; p++) s += s_part2[p][tid];
        out[tid] = s;
    }
}

// ---------------------------------------------------------------------------
extern "C" void kernel_launch(void* const* d_in, const int* in_sizes, int n_in,
                              void* d_out, int out_size) {
    const float* x       = (const float*)d_in[0];
    const float* centres = (const float*)d_in[1];
    const float* sharp   = (const float*)d_in[2];
    float*       out     = (float*)d_out;

    const size_t mst_smem = (size_t)NROWS_SMEM * N_SEQ * sizeof(unsigned); // 224 KB
    cudaFuncSetAttribute(k_mst, cudaFuncAttributeMaxDynamicSharedMemorySize, (int)mst_smem);

    k_meanfeat<<<N_SEQ, 512>>>(x);
    k_dist<<<N_SEQ, 256>>>();
    k_mst<<<1, 512, mst_smem>>>(centres, sharp, out);
}